// round 2
// baseline (speedup 1.0000x reference)
#include <cuda_runtime.h>

#define DIM   1024
#define BATCH 4
#define SEQ   1024
#define NHEAD 16
#define HD    64
#define NROWS (BATCH*SEQ)     /* 4096 */
#define BH    (BATCH*NHEAD)   /* 64   */
#define TOPK  32

#define F_INF   __int_as_float(0x7f800000)
#define F_NINF  __int_as_float(0xff800000)

// ---------------- scratch (device globals; no allocation allowed) ----------
__device__ float g_xn[(size_t)NROWS*DIM];          // 16 MB  normalized x
__device__ float g_q[(size_t)BH*SEQ*HD];           // 16 MB  [b,h,n,d] (pre-scaled)
__device__ float g_k[(size_t)BH*SEQ*HD];           // 16 MB
__device__ float g_v[(size_t)BH*SEQ*HD];           // 16 MB
__device__ float g_sim[(size_t)BH*SEQ*SEQ];        // 256 MB [b,h,i,j]
__device__ float g_xsum[(size_t)NROWS*DIM];        // 16 MB  [b,n,(h d)] (pre-permuted)
__device__ unsigned g_mm[2];                       // encoded min / max

// monotone float<->uint encoding for atomic min/max
__device__ __forceinline__ unsigned fenc(float f) {
    unsigned u = __float_as_uint(f);
    return (u & 0x80000000u) ? ~u : (u | 0x80000000u);
}
__device__ __forceinline__ float fdec(unsigned u) {
    return __uint_as_float((u & 0x80000000u) ? (u ^ 0x80000000u) : ~u);
}

__global__ void init_mm_kernel() {
    g_mm[0] = 0xFFFFFFFFu;   // running min (encoded)
    g_mm[1] = 0u;            // running max (encoded)
}

// ---------------- LayerNorm: one block per row -----------------------------
__global__ void layernorm_kernel(const float* __restrict__ x,
                                 const float* __restrict__ gamma,
                                 const float* __restrict__ beta) {
    int row = blockIdx.x, tid = threadIdx.x;           // 256 threads, 4 elems each
    const float4* xr = reinterpret_cast<const float4*>(x + (size_t)row * DIM);
    float4 xv = xr[tid];
    float s  = xv.x + xv.y + xv.z + xv.w;
    float ss = fmaf(xv.x, xv.x, fmaf(xv.y, xv.y, fmaf(xv.z, xv.z, xv.w * xv.w)));
    #pragma unroll
    for (int o = 16; o; o >>= 1) {
        s  += __shfl_xor_sync(0xffffffffu, s,  o);
        ss += __shfl_xor_sync(0xffffffffu, ss, o);
    }
    __shared__ float rs[8], rss[8];
    __shared__ float sm_mean, sm_inv;
    int w = tid >> 5, l = tid & 31;
    if (!l) { rs[w] = s; rss[w] = ss; }
    __syncthreads();
    if (tid == 0) {
        float S = 0.f, SS = 0.f;
        #pragma unroll
        for (int i = 0; i < 8; i++) { S += rs[i]; SS += rss[i]; }
        float mean = S * (1.f / DIM);
        float var  = SS * (1.f / DIM) - mean * mean;
        sm_mean = mean;
        sm_inv  = rsqrtf(var + 1e-5f);
    }
    __syncthreads();
    float mean = sm_mean, inv = sm_inv;
    float4 gv = reinterpret_cast<const float4*>(gamma)[tid];
    float4 bv = reinterpret_cast<const float4*>(beta)[tid];
    float4 o;
    o.x = (xv.x - mean) * inv * gv.x + bv.x;
    o.y = (xv.y - mean) * inv * gv.y + bv.y;
    o.z = (xv.z - mean) * inv * gv.z + bv.z;
    o.w = (xv.w - mean) * inv * gv.w + bv.w;
    reinterpret_cast<float4*>(g_xn)[(size_t)row * (DIM / 4) + tid] = o;
}

// ---------------- 128x128x8 register-blocked SGEMM (C = A @ B^T) -----------
// EPI 0: sim      A=g_q[bz], B=g_k[bz], C=g_sim[bz]
// EPI 1: qkv      A=g_xn,    B=w_qkv,   scatter into g_q/g_k/g_v (q scaled)
// EPI 2: out      A=g_xsum,  B=w_out,   C=out + bias
template<int EPI, int N, int K, int LDA, int LDB>
__global__ __launch_bounds__(256, 2)
void sgemm_kernel(const float* __restrict__ Bparam,
                  float* __restrict__ Cparam,
                  const float* __restrict__ bias) {
    const float* A;
    const float* B;
    if (EPI == 0) {
        size_t off = (size_t)blockIdx.z * SEQ * HD;
        A = g_q + off;  B = g_k + off;
    } else if (EPI == 1) {
        A = g_xn;  B = Bparam;
    } else {
        A = g_xsum;  B = Bparam;
    }

    __shared__ float As[8][128];
    __shared__ float Bs[8][128];

    int tid = threadIdx.x;
    int bm = blockIdx.y * 128, bn = blockIdx.x * 128;
    int ldRow = tid >> 1, ldCol = (tid & 1) * 4;
    const float* Ap = A + (size_t)(bm + ldRow) * LDA + ldCol;
    const float* Bp = B + (size_t)(bn + ldRow) * LDB + ldCol;

    float acc[8][8] = {};
    int ty = tid >> 4, tx = tid & 15;

    for (int k0 = 0; k0 < K; k0 += 8) {
        float4 av = *(const float4*)(Ap + k0);
        float4 bv = *(const float4*)(Bp + k0);
        As[ldCol + 0][ldRow] = av.x; As[ldCol + 1][ldRow] = av.y;
        As[ldCol + 2][ldRow] = av.z; As[ldCol + 3][ldRow] = av.w;
        Bs[ldCol + 0][ldRow] = bv.x; Bs[ldCol + 1][ldRow] = bv.y;
        Bs[ldCol + 2][ldRow] = bv.z; Bs[ldCol + 3][ldRow] = bv.w;
        __syncthreads();
        #pragma unroll
        for (int kk = 0; kk < 8; kk++) {
            float a[8], b[8];
            *(float4*)(a)     = *(const float4*)&As[kk][ty * 8];
            *(float4*)(a + 4) = *(const float4*)&As[kk][ty * 8 + 4];
            *(float4*)(b)     = *(const float4*)&Bs[kk][tx * 8];
            *(float4*)(b + 4) = *(const float4*)&Bs[kk][tx * 8 + 4];
            #pragma unroll
            for (int i = 0; i < 8; i++)
                #pragma unroll
                for (int j = 0; j < 8; j++)
                    acc[i][j] = fmaf(a[i], b[j], acc[i][j]);
        }
        __syncthreads();
    }

    #pragma unroll
    for (int i = 0; i < 8; i++) {
        int m = bm + ty * 8 + i;
        #pragma unroll
        for (int j = 0; j < 8; j++) {
            int n = bn + tx * 8 + j;
            float v = acc[i][j];
            if (EPI == 0) {
                g_sim[(size_t)blockIdx.z * SEQ * SEQ + (size_t)m * N + n] = v;
            } else if (EPI == 1) {
                int which = n >> 10;             // 0=q 1=k 2=v
                int hh = (n & 1023) >> 6;
                int dd = n & 63;
                int bb = m >> 10;
                int nn = m & 1023;
                size_t o = (((size_t)(bb * NHEAD + hh)) * SEQ + nn) * HD + dd;
                if (which == 0)      g_q[o] = v * 0.125f;   // d^-0.5, d=64
                else if (which == 1) g_k[o] = v;
                else                 g_v[o] = v;
            } else {
                Cparam[(size_t)m * N + n] = v + bias[n];
            }
        }
    }
}

// ---------------- top-32 select + gather-sum: one warp per query row -------
__global__ void topk_gather_kernel() {
    int warp = threadIdx.x >> 5;
    int lane = threadIdx.x & 31;
    int row  = blockIdx.x * 4 + warp;          // ((b*16+h)*1024 + nq), 65536 rows
    int bh   = row >> 10;

    const float* srow = g_sim + (size_t)row * SEQ;
    float vals[32];
    #pragma unroll
    for (int i = 0; i < 32; i++) vals[i] = srow[i * 32 + lane];  // j = i*32+lane

    int myidx = 0;
    #pragma unroll 1
    for (int r = 0; r < TOPK; r++) {
        // local argmax over 32 register values
        float best = vals[0]; int bi = 0;
        #pragma unroll
        for (int i = 1; i < 32; i++)
            if (vals[i] > best) { best = vals[i]; bi = i; }
        unsigned u = fenc(best);
        unsigned long long p = ((unsigned long long)u << 32) | (unsigned)(bi * 32 + lane);
        #pragma unroll
        for (int off = 16; off; off >>= 1) {
            unsigned long long q2 = __shfl_xor_sync(0xffffffffu, p, off);
            if (q2 > p) p = q2;
        }
        int widx = (int)(p & 0xffffffffu);     // winning key index, all lanes agree
        bool mine = (widx & 31) == lane;
        int slot  = widx >> 5;
        #pragma unroll
        for (int i = 0; i < 32; i++)
            if (mine && slot == i) vals[i] = F_NINF;
        if (lane == r) myidx = widx;           // lane r remembers round-r winner
    }

    // unweighted gather-sum of the 32 selected V rows
    const float* vbase = g_v + (size_t)bh * SEQ * HD;
    float a0 = 0.f, a1 = 0.f;
    #pragma unroll 1
    for (int r = 0; r < TOPK; r++) {
        int idx = __shfl_sync(0xffffffffu, myidx, r);
        const float* vr = vbase + (size_t)idx * HD;
        a0 += vr[lane];
        a1 += vr[lane + 32];
    }

    int bb = row >> 14;            // /(16*1024)
    int hh = (row >> 10) & 15;
    int nq = row & 1023;
    size_t o = ((size_t)(bb * SEQ + nq)) * DIM + hh * HD;   // pre-permuted [b,n,(h d)]
    g_xsum[o + lane]      = a0;
    g_xsum[o + lane + 32] = a1;
}

// ---------------- global min/max over g_xsum -------------------------------
__global__ void minmax_kernel() {
    float mn = F_INF, mx = F_NINF;
    int stride = gridDim.x * blockDim.x;
    const float4* p = reinterpret_cast<const float4*>(g_xsum);
    for (int i = blockIdx.x * blockDim.x + threadIdx.x; i < NROWS * DIM / 4; i += stride) {
        float4 v = p[i];
        mn = fminf(mn, fminf(fminf(v.x, v.y), fminf(v.z, v.w)));
        mx = fmaxf(mx, fmaxf(fmaxf(v.x, v.y), fmaxf(v.z, v.w)));
    }
    #pragma unroll
    for (int o = 16; o; o >>= 1) {
        mn = fminf(mn, __shfl_xor_sync(0xffffffffu, mn, o));
        mx = fmaxf(mx, __shfl_xor_sync(0xffffffffu, mx, o));
    }
    __shared__ float smn[8], smx[8];
    int w = threadIdx.x >> 5, l = threadIdx.x & 31;
    if (!l) { smn[w] = mn; smx[w] = mx; }
    __syncthreads();
    if (threadIdx.x == 0) {
        #pragma unroll
        for (int i = 1; i < 8; i++) { mn = fminf(mn, smn[i]); mx = fmaxf(mx, smx[i]); }
        atomicMin(&g_mm[0], fenc(mn));
        atomicMax(&g_mm[1], fenc(mx));
    }
}

// ---------------- exp((x-min)/(max-min)) in place --------------------------
__global__ void norm_exp_kernel() {
    float mn = fdec(g_mm[0]);
    float mx = fdec(g_mm[1]);
    float inv = 1.0f / (mx - mn);
    int stride = gridDim.x * blockDim.x;
    float4* p = reinterpret_cast<float4*>(g_xsum);
    for (int i = blockIdx.x * blockDim.x + threadIdx.x; i < NROWS * DIM / 4; i += stride) {
        float4 v = p[i];
        v.x = expf((v.x - mn) * inv);
        v.y = expf((v.y - mn) * inv);
        v.z = expf((v.z - mn) * inv);
        v.w = expf((v.w - mn) * inv);
        p[i] = v;
    }
}

// ---------------- launch ---------------------------------------------------
extern "C" void kernel_launch(void* const* d_in, const int* in_sizes, int n_in,
                              void* d_out, int out_size) {
    const float* x      = (const float*)d_in[0];
    const float* gamma  = (const float*)d_in[1];
    const float* beta   = (const float*)d_in[2];
    const float* w_qkv  = (const float*)d_in[3];
    const float* w_out  = (const float*)d_in[4];
    const float* b_out  = (const float*)d_in[5];
    // d_in[6] = topk (fixed at 32 for this problem instance)
    float* out = (float*)d_out;

    init_mm_kernel<<<1, 1>>>();
    layernorm_kernel<<<NROWS, 256>>>(x, gamma, beta);
    // qkv projection: [4096,1024] @ [3072,1024]^T, scatter epilogue
    sgemm_kernel<1, 3 * DIM, DIM, DIM, DIM><<<dim3(24, 32, 1), 256>>>(w_qkv, nullptr, nullptr);
    // sim: 64 batched [1024,64] @ [1024,64]^T
    sgemm_kernel<0, SEQ, HD, HD, HD><<<dim3(8, 8, BH), 256>>>(nullptr, nullptr, nullptr);
    // top-32 select + gather-sum (softmax skipped: monotone w.r.t. sim)
    topk_gather_kernel<<<BH * SEQ / 4, 128>>>();
    minmax_kernel<<<1024, 256>>>();
    norm_exp_kernel<<<1024, 256>>>();
    // final projection: [4096,1024] @ [1024,1024]^T + bias
    sgemm_kernel<2, DIM, DIM, DIM, DIM><<<dim3(8, 32, 1), 256>>>(w_out, out, b_out);
}

// round 7
// speedup vs baseline: 1.6404x; 1.6404x over previous
#include <cuda_runtime.h>
#include <cuda_bf16.h>
#include <cstdint>

#define DIM   1024
#define BATCH 4
#define SEQ   1024
#define NHEAD 16
#define HD    64
#define NROWS (BATCH*SEQ)     /* 4096 */
#define BH    (BATCH*NHEAD)   /* 64   */
#define TOPK  32

#define F_INF   __int_as_float(0x7f800000)
#define F_NINF  __int_as_float(0xff800000)

// ---------------- scratch (device globals; no allocation allowed) ----------
__device__ float g_xn[(size_t)NROWS*DIM];          // 16 MB  normalized x
__device__ float g_q[(size_t)BH*SEQ*HD];           // 16 MB  [b,h,n,d] (pre-scaled)
__device__ float g_k[(size_t)BH*SEQ*HD];           // 16 MB
__device__ float g_v[(size_t)BH*SEQ*HD];           // 16 MB
__device__ float g_sim[(size_t)BH*SEQ*SEQ];        // 256 MB [b,h,i,j]
__device__ float g_xsum[(size_t)NROWS*DIM];        // 16 MB  [b,n,(h d)] (pre-permuted)
__device__ unsigned g_mm[2];                       // encoded min / max

// ---------------- helpers --------------------------------------------------
__device__ __forceinline__ uint32_t smem_u32(const void* p) {
    uint32_t a;
    asm("{ .reg .u64 t; cvta.to.shared.u64 t, %1; cvt.u32.u64 %0, t; }"
        : "=r"(a) : "l"(p));
    return a;
}

// fp32 float4 -> packed bf16 hi (uint2) and lo residual (uint2)
__device__ __forceinline__ void f4_hilo(float4 v, uint2& hi, uint2& lo) {
    __nv_bfloat16 h0 = __float2bfloat16(v.x), h1 = __float2bfloat16(v.y);
    __nv_bfloat16 h2 = __float2bfloat16(v.z), h3 = __float2bfloat16(v.w);
    __nv_bfloat16 l0 = __float2bfloat16(v.x - __bfloat162float(h0));
    __nv_bfloat16 l1 = __float2bfloat16(v.y - __bfloat162float(h1));
    __nv_bfloat16 l2 = __float2bfloat16(v.z - __bfloat162float(h2));
    __nv_bfloat16 l3 = __float2bfloat16(v.w - __bfloat162float(h3));
    hi.x = (uint32_t)__bfloat16_as_ushort(h0) | ((uint32_t)__bfloat16_as_ushort(h1) << 16);
    hi.y = (uint32_t)__bfloat16_as_ushort(h2) | ((uint32_t)__bfloat16_as_ushort(h3) << 16);
    lo.x = (uint32_t)__bfloat16_as_ushort(l0) | ((uint32_t)__bfloat16_as_ushort(l1) << 16);
    lo.y = (uint32_t)__bfloat16_as_ushort(l2) | ((uint32_t)__bfloat16_as_ushort(l3) << 16);
}

__device__ __forceinline__ unsigned fenc(float f) {
    unsigned u = __float_as_uint(f);
    return (u & 0x80000000u) ? ~u : (u | 0x80000000u);
}
__device__ __forceinline__ float fdec(unsigned u) {
    return __uint_as_float((u & 0x80000000u) ? (u ^ 0x80000000u) : ~u);
}

#define LDSM_X4(r, a) \
    asm volatile("ldmatrix.sync.aligned.m8n8.x4.shared.b16 {%0,%1,%2,%3}, [%4];" \
        : "=r"((r)[0]), "=r"((r)[1]), "=r"((r)[2]), "=r"((r)[3]) : "r"(a))
#define LDSM_X2(r, a) \
    asm volatile("ldmatrix.sync.aligned.m8n8.x2.shared.b16 {%0,%1}, [%2];" \
        : "=r"((r)[0]), "=r"((r)[1]) : "r"(a))
#define MMA16816(d, a, b) \
    asm volatile("mma.sync.aligned.m16n8k16.row.col.f32.bf16.bf16.f32 " \
        "{%0,%1,%2,%3}, {%4,%5,%6,%7}, {%8,%9}, {%0,%1,%2,%3};" \
        : "+f"((d)[0]), "+f"((d)[1]), "+f"((d)[2]), "+f"((d)[3]) \
        : "r"((a)[0]), "r"((a)[1]), "r"((a)[2]), "r"((a)[3]), "r"((b)[0]), "r"((b)[1]))

__global__ void init_mm_kernel() {
    g_mm[0] = 0xFFFFFFFFu;
    g_mm[1] = 0u;
}

// ---------------- LayerNorm: one block per row -----------------------------
__global__ void layernorm_kernel(const float* __restrict__ x,
                                 const float* __restrict__ gamma,
                                 const float* __restrict__ beta) {
    int row = blockIdx.x, tid = threadIdx.x;
    const float4* xr = reinterpret_cast<const float4*>(x + (size_t)row * DIM);
    float4 xv = xr[tid];
    float s  = xv.x + xv.y + xv.z + xv.w;
    float ss = fmaf(xv.x, xv.x, fmaf(xv.y, xv.y, fmaf(xv.z, xv.z, xv.w * xv.w)));
    #pragma unroll
    for (int o = 16; o; o >>= 1) {
        s  += __shfl_xor_sync(0xffffffffu, s,  o);
        ss += __shfl_xor_sync(0xffffffffu, ss, o);
    }
    __shared__ float rs[8], rss[8];
    __shared__ float sm_mean, sm_inv;
    int w = tid >> 5, l = tid & 31;
    if (!l) { rs[w] = s; rss[w] = ss; }
    __syncthreads();
    if (tid == 0) {
        float S = 0.f, SS = 0.f;
        #pragma unroll
        for (int i = 0; i < 8; i++) { S += rs[i]; SS += rss[i]; }
        float mean = S * (1.f / DIM);
        float var  = SS * (1.f / DIM) - mean * mean;
        sm_mean = mean;
        sm_inv  = rsqrtf(var + 1e-5f);
    }
    __syncthreads();
    float mean = sm_mean, inv = sm_inv;
    float4 gv = reinterpret_cast<const float4*>(gamma)[tid];
    float4 bv = reinterpret_cast<const float4*>(beta)[tid];
    float4 o;
    o.x = (xv.x - mean) * inv * gv.x + bv.x;
    o.y = (xv.y - mean) * inv * gv.y + bv.y;
    o.z = (xv.z - mean) * inv * gv.z + bv.z;
    o.w = (xv.w - mean) * inv * gv.w + bv.w;
    reinterpret_cast<float4*>(g_xn)[(size_t)row * (DIM / 4) + tid] = o;
}

// ---------------- HMMA bf16x3 GEMM (C = A @ B^T, fp32 in/out) --------------
// 128x128 CTA tile, K-chunk 32, 8 warps (2x4), warp tile 64x32.
// SMEM rows padded to 80B -> conflict-free ldmatrix.
// EPI 0: sim   A=g_q[bz], B=g_k[bz] -> g_sim
// EPI 1: qkv   A=g_xn,    B=w_qkv   -> scatter q(scaled)/k/v
// EPI 2: out   A=g_xsum,  B=w_out   -> C + bias
#define RSTRIDE 80

template<int EPI, int KTOT, int LDA, int LDB>
__global__ __launch_bounds__(256)
void mma_gemm(const float* __restrict__ Bw, float* __restrict__ C,
              const float* __restrict__ bias) {
    __shared__ __align__(16) char sAhi[128 * RSTRIDE];
    __shared__ __align__(16) char sAlo[128 * RSTRIDE];
    __shared__ __align__(16) char sBhi[128 * RSTRIDE];
    __shared__ __align__(16) char sBlo[128 * RSTRIDE];

    const float* A;
    const float* B;
    if (EPI == 0) {
        size_t off = (size_t)blockIdx.z * SEQ * HD;
        A = g_q + off;  B = g_k + off;
    } else if (EPI == 1) { A = g_xn;   B = Bw; }
    else                 { A = g_xsum; B = Bw; }

    int tid = threadIdx.x;
    int bm = blockIdx.y * 128, bn = blockIdx.x * 128;

    // loader mapping: thread t -> row t>>1, k-halfchunk (t&1)*16, 4x float4 each
    int lrow = tid >> 1, lcb = (tid & 1) * 16;
    const float* Ap = A + (size_t)(bm + lrow) * LDA + lcb;
    const float* Bp = B + (size_t)(bn + lrow) * LDB + lcb;

    float4 ar[4], br[4];
    #pragma unroll
    for (int i = 0; i < 4; i++) {
        ar[i] = *(const float4*)(Ap + i * 4);
        br[i] = *(const float4*)(Bp + i * 4);
    }

    int w = tid >> 5, l = tid & 31;
    int wm = w >> 2, wn = w & 3;           // 2 x 4 warp grid

    uint32_t aAhi = smem_u32(sAhi), aAlo = smem_u32(sAlo);
    uint32_t aBhi = smem_u32(sBhi), aBlo = smem_u32(sBlo);
    // per-lane ldmatrix offsets
    uint32_t aLane = (uint32_t)(((l & 7) + ((l >> 3) & 1) * 8) * RSTRIDE + (l >> 4) * 16);
    uint32_t bLane = (uint32_t)((l & 7) * RSTRIDE + ((l >> 3) & 1) * 16);
    uint32_t aWarp = (uint32_t)(wm * 64 * RSTRIDE);
    uint32_t bWarp = (uint32_t)(wn * 32 * RSTRIDE);

    float acc[4][4][4] = {};

    const int NS = KTOT / 32;
    #pragma unroll 1
    for (int s = 0; s < NS; s++) {
        if (s) __syncthreads();            // previous compute done, smem reusable
        #pragma unroll
        for (int i = 0; i < 4; i++) {
            uint32_t off = (uint32_t)(lrow * RSTRIDE + (lcb + i * 4) * 2);
            uint2 h, lo;
            f4_hilo(ar[i], h, lo);
            *(uint2*)(sAhi + off) = h;  *(uint2*)(sAlo + off) = lo;
            f4_hilo(br[i], h, lo);
            *(uint2*)(sBhi + off) = h;  *(uint2*)(sBlo + off) = lo;
        }
        __syncthreads();
        if (s + 1 < NS) {                  // prefetch next chunk during HMMA
            #pragma unroll
            for (int i = 0; i < 4; i++) {
                ar[i] = *(const float4*)(Ap + (s + 1) * 32 + i * 4);
                br[i] = *(const float4*)(Bp + (s + 1) * 32 + i * 4);
            }
        }
        #pragma unroll
        for (int kk = 0; kk < 32; kk += 16) {
            uint32_t af[4][2][4];
            #pragma unroll
            for (int mi = 0; mi < 4; mi++) {
                uint32_t o = aWarp + (uint32_t)(mi * 16 * RSTRIDE + kk * 2) + aLane;
                LDSM_X4(af[mi][0], aAhi + o);
                LDSM_X4(af[mi][1], aAlo + o);
            }
            uint32_t bf[4][2][2];
            #pragma unroll
            for (int nj = 0; nj < 4; nj++) {
                uint32_t o = bWarp + (uint32_t)(nj * 8 * RSTRIDE + kk * 2) + bLane;
                LDSM_X2(bf[nj][0], aBhi + o);
                LDSM_X2(bf[nj][1], aBlo + o);
            }
            #pragma unroll
            for (int mi = 0; mi < 4; mi++)
                #pragma unroll
                for (int nj = 0; nj < 4; nj++) {
                    MMA16816(acc[mi][nj], af[mi][0], bf[nj][0]);   // hi*hi
                    MMA16816(acc[mi][nj], af[mi][0], bf[nj][1]);   // hi*lo
                    MMA16816(acc[mi][nj], af[mi][1], bf[nj][0]);   // lo*hi
                }
        }
    }

    // ---------------- epilogue from register accumulators ----------------
    #pragma unroll
    for (int mi = 0; mi < 4; mi++) {
        int row0 = bm + wm * 64 + mi * 16 + (l >> 2);
        #pragma unroll
        for (int nj = 0; nj < 4; nj++) {
            int col = bn + wn * 32 + nj * 8 + (l & 3) * 2;
            #pragma unroll
            for (int half = 0; half < 2; half++) {
                int m = row0 + half * 8;
                float v0 = acc[mi][nj][half * 2 + 0];
                float v1 = acc[mi][nj][half * 2 + 1];
                if (EPI == 0) {
                    float2* dst = (float2*)(g_sim + (size_t)blockIdx.z * SEQ * SEQ
                                            + (size_t)m * SEQ + col);
                    *dst = make_float2(v0, v1);
                } else if (EPI == 1) {
                    int which = col >> 10;          // 0=q 1=k 2=v
                    int hh = (col & 1023) >> 6;
                    int dd = col & 63;
                    int bb = m >> 10, nn = m & 1023;
                    size_t o = (((size_t)(bb * NHEAD + hh)) * SEQ + nn) * HD + dd;
                    float sc = (which == 0) ? 0.125f : 1.0f;   // q pre-scale d^-0.5
                    float* dst = (which == 0 ? g_q : which == 1 ? g_k : g_v) + o;
                    *(float2*)dst = make_float2(v0 * sc, v1 * sc);
                } else {
                    float2* dst = (float2*)(C + (size_t)m * DIM + col);
                    *dst = make_float2(v0 + bias[col], v1 + bias[col + 1]);
                }
            }
        }
    }
}

// ---------------- top-32 select + gather-sum: one warp per query row -------
__global__ void topk_gather_kernel() {
    int warp = threadIdx.x >> 5;
    int lane = threadIdx.x & 31;
    int row  = blockIdx.x * 4 + warp;          // ((b*16+h)*1024 + nq)
    int bh   = row >> 10;

    const float* srow = g_sim + (size_t)row * SEQ;
    float vals[32];
    #pragma unroll
    for (int i = 0; i < 32; i++) vals[i] = srow[i * 32 + lane];   // j = i*32+lane

    // per-lane running argmax over its 32 values
    float best = vals[0]; int bi = 0;
    #pragma unroll
    for (int i = 1; i < 32; i++)
        if (vals[i] > best) { best = vals[i]; bi = i; }

    int myidx = 0;
    #pragma unroll 1
    for (int r = 0; r < TOPK; r++) {
        unsigned e = fenc(best);
        unsigned wmax = __reduce_max_sync(0xffffffffu, e);
        unsigned msk = __ballot_sync(0xffffffffu, e == wmax);
        int wl = __ffs(msk) - 1;
        int wbi = __shfl_sync(0xffffffffu, bi, wl);
        int widx = wbi * 32 + wl;              // winning key index
        if (lane == r) myidx = widx;
        if (lane == wl) {                       // winner rescans its registers
            float nb = F_NINF; int nbi = 0;
            #pragma unroll
            for (int i = 0; i < 32; i++) {
                if (i == bi) vals[i] = F_NINF;
                if (vals[i] > nb) { nb = vals[i]; nbi = i; }
            }
            best = nb; bi = nbi;
        }
    }

    // unweighted gather-sum of the 32 selected V rows
    const float* vbase = g_v + (size_t)bh * SEQ * HD;
    float a0 = 0.f, a1 = 0.f;
    #pragma unroll 1
    for (int r = 0; r < TOPK; r++) {
        int idx = __shfl_sync(0xffffffffu, myidx, r);
        const float* vr = vbase + (size_t)idx * HD;
        a0 += vr[lane];
        a1 += vr[lane + 32];
    }

    int bb = row >> 14;
    int hh = (row >> 10) & 15;
    int nq = row & 1023;
    size_t o = ((size_t)(bb * SEQ + nq)) * DIM + hh * HD;   // [b,n,(h d)]
    g_xsum[o + lane]      = a0;
    g_xsum[o + lane + 32] = a1;
}

// ---------------- global min/max over g_xsum -------------------------------
__global__ void minmax_kernel() {
    float mn = F_INF, mx = F_NINF;
    int stride = gridDim.x * blockDim.x;
    const float4* p = reinterpret_cast<const float4*>(g_xsum);
    for (int i = blockIdx.x * blockDim.x + threadIdx.x; i < NROWS * DIM / 4; i += stride) {
        float4 v = p[i];
        mn = fminf(mn, fminf(fminf(v.x, v.y), fminf(v.z, v.w)));
        mx = fmaxf(mx, fmaxf(fmaxf(v.x, v.y), fmaxf(v.z, v.w)));
    }
    #pragma unroll
    for (int o = 16; o; o >>= 1) {
        mn = fminf(mn, __shfl_xor_sync(0xffffffffu, mn, o));
        mx = fmaxf(mx, __shfl_xor_sync(0xffffffffu, mx, o));
    }
    __shared__ float smn[8], smx[8];
    int w = threadIdx.x >> 5, l = threadIdx.x & 31;
    if (!l) { smn[w] = mn; smx[w] = mx; }
    __syncthreads();
    if (threadIdx.x == 0) {
        #pragma unroll
        for (int i = 1; i < 8; i++) { mn = fminf(mn, smn[i]); mx = fmaxf(mx, smx[i]); }
        atomicMin(&g_mm[0], fenc(mn));
        atomicMax(&g_mm[1], fenc(mx));
    }
}

// ---------------- exp((x-min)/(max-min)) in place --------------------------
__global__ void norm_exp_kernel() {
    float mn = fdec(g_mm[0]);
    float mx = fdec(g_mm[1]);
    float inv = 1.0f / (mx - mn);
    int stride = gridDim.x * blockDim.x;
    float4* p = reinterpret_cast<float4*>(g_xsum);
    for (int i = blockIdx.x * blockDim.x + threadIdx.x; i < NROWS * DIM / 4; i += stride) {
        float4 v = p[i];
        v.x = expf((v.x - mn) * inv);
        v.y = expf((v.y - mn) * inv);
        v.z = expf((v.z - mn) * inv);
        v.w = expf((v.w - mn) * inv);
        p[i] = v;
    }
}

// ---------------- launch ---------------------------------------------------
extern "C" void kernel_launch(void* const* d_in, const int* in_sizes, int n_in,
                              void* d_out, int out_size) {
    const float* x      = (const float*)d_in[0];
    const float* gamma  = (const float*)d_in[1];
    const float* beta   = (const float*)d_in[2];
    const float* w_qkv  = (const float*)d_in[3];
    const float* w_out  = (const float*)d_in[4];
    const float* b_out  = (const float*)d_in[5];
    float* out = (float*)d_out;

    init_mm_kernel<<<1, 1>>>();
    layernorm_kernel<<<NROWS, 256>>>(x, gamma, beta);
    // qkv: [4096,1024] @ [3072,1024]^T (HMMA bf16x3), scatter epilogue
    mma_gemm<1, DIM, DIM, DIM><<<dim3(24, 32, 1), 256>>>(w_qkv, nullptr, nullptr);
    // sim: 64 batched [1024,64] @ [1024,64]^T
    mma_gemm<0, HD, HD, HD><<<dim3(8, 8, BH), 256>>>(nullptr, nullptr, nullptr);
    // top-32 select + gather-sum (softmax skipped: monotone w.r.t. sim)
    topk_gather_kernel<<<BH * SEQ / 4, 128>>>();
    minmax_kernel<<<1024, 256>>>();
    norm_exp_kernel<<<1024, 256>>>();
    // out: [4096,1024] @ [1024,1024]^T + bias
    mma_gemm<2, DIM, DIM, DIM><<<dim3(8, 32, 1), 256>>>(w_out, out, b_out);
}